// round 12
// baseline (speedup 1.0000x reference)
#include <cuda_runtime.h>

#define HH 512
#define WW 512
#define NPIX (HH*WW)
#define NIMG 32
#define SMOOTHF 1e-5f
#define KF 5            // fused skeletonize iterations per pass
#define HALO_C 12       // column halo per side (>= 2*KF, multiple of 4)
#define OWNC 104        // owned columns per warp window (128 - 2*HALO_C)
#define CTILES 5        // ceil(512/104)
#define RB 128          // rows per band
#define NBANDS 4
#define LAGOUT 14       // output lag: 3*(KF-1)+2
#define NSTEPS 154      // RB + 25 + 1 (even, x0 = r0-11)
#define ALLM 0xffffffffu
#define NSKEL (2*NIMG*CTILES*NBANDS)   // 1280 pass-1 skel blocks
#define NDICE 8192                     // dice backfill blocks in pass 1
#define NSKEL2 (NIMG*CTILES*NBANDS)    // 640 pass-2 dual blocks

// Scratch (device globals: no allocation allowed; zero-initialized at load)
__device__ float    g_tmp [2][NIMG*NPIX];   // after iterations 1..5
__device__ float    g_acc [NIMG][8];        // 0:sp 1:st 2:spt 3:ssp 4:sst 5:sspt
__device__ unsigned g_ctr;                  // pass-2 completion counter

__device__ __forceinline__ float sigf(float x){
    return __fdividef(1.0f, 1.0f + __expf(-x));
}

// ---- plain-dice backfill path (runs as extra blocks of the pass-1 launch) ----
// One warp handles 1024 contiguous pixels of one image: 8 float4 per lane.
__device__ __forceinline__ void dice_path(int idx, const float* __restrict__ logits,
                                          const float* __restrict__ target){
    int img   = idx >> 8;          // 256 warps per image
    int chunk = idx & 255;
    int lane  = threadIdx.x;
    const float4* Lp = (const float4*)(logits + (size_t)img*NPIX);
    const float4* Tp = (const float4*)(target + (size_t)img*NPIX);
    int base = chunk*256 + lane;
    float4 l[8], t[8];
    #pragma unroll
    for (int i = 0; i < 8; i++) l[i] = Lp[base + i*32];
    #pragma unroll
    for (int i = 0; i < 8; i++) t[i] = Tp[base + i*32];
    float sp=0.f, st=0.f, spt=0.f;
    #pragma unroll
    for (int i = 0; i < 8; i++){
        float p;
        p = sigf(l[i].x); sp += p; st += t[i].x; spt += p*t[i].x;
        p = sigf(l[i].y); sp += p; st += t[i].y; spt += p*t[i].y;
        p = sigf(l[i].z); sp += p; st += t[i].z; spt += p*t[i].z;
        p = sigf(l[i].w); sp += p; st += t[i].w; spt += p*t[i].w;
    }
    #pragma unroll
    for (int o=16;o;o>>=1){
        sp  += __shfl_down_sync(ALLM, sp , o);
        st  += __shfl_down_sync(ALLM, st , o);
        spt += __shfl_down_sync(ALLM, spt, o);
    }
    if (lane == 0){
        atomicAdd(&g_acc[img][0], sp);
        atomicAdd(&g_acc[img][1], st);
        atomicAdd(&g_acc[img][2], spt);
    }
}

// One decoupled pipeline stage j. Fed row xr = x - 3j (value in CIN).
// State: sN[j] = In_j[xr-1], sO[j] = In_j[xr-2], eN[j] = E_j[xr-2],
// eO[j] = E_j[xr-3]. Computes E_j[xr-1] and O_j[xr-2] -> OUT.
// Rotation by role swap (zero MOVs). Output is NOT boundary-forced: at
// OOB rows/cols it becomes +INF or NaN; fminf/fmaxf drop NaN operands, so
// downstream min chains treat it exactly as the +INF sentinel. Only the
// eroded field needs explicit forcing (en -> -INF at OOB), since it feeds
// a max-pool where the neutral element differs.
#define STAGE(j, sN, sO, eN, eO, CIN, OUT)                                    \
{                                                                             \
    float vm0 = fminf(sO[j][0], fminf(sN[j][0], CIN[0]));                     \
    float vm1 = fminf(sO[j][1], fminf(sN[j][1], CIN[1]));                     \
    float vm2 = fminf(sO[j][2], fminf(sN[j][2], CIN[2]));                     \
    float vm3 = fminf(sO[j][3], fminf(sN[j][3], CIN[3]));                     \
    float Lm = __shfl_up_sync  (ALLM, vm3, 1);                                \
    float Rm = __shfl_down_sync(ALLM, vm0, 1);                                \
    float m01 = fminf(vm0, vm1), m12 = fminf(vm1, vm2), m23 = fminf(vm2, vm3);\
    float en0 = fminf(Lm,  m01);                                              \
    float en1 = fminf(m01, vm2);                                              \
    float en2 = fminf(m12, vm3);                                              \
    float en3 = fminf(m23, Rm);                                               \
    if (!(colok && (unsigned)(x - 3*(j) - 1) < (unsigned)HH)){                \
        en0 = NINF; en1 = NINF; en2 = NINF; en3 = NINF;                       \
    }                                                                         \
    float tx0 = fmaxf(eO[j][0], fmaxf(eN[j][0], en0));                        \
    float tx1 = fmaxf(eO[j][1], fmaxf(eN[j][1], en1));                        \
    float tx2 = fmaxf(eO[j][2], fmaxf(eN[j][2], en2));                        \
    float tx3 = fmaxf(eO[j][3], fmaxf(eN[j][3], en3));                        \
    float Lx = __shfl_up_sync  (ALLM, tx3, 1);                                \
    float Rx = __shfl_down_sync(ALLM, tx0, 1);                                \
    float M01 = fmaxf(tx0, tx1), M12 = fmaxf(tx1, tx2), M23 = fmaxf(tx2, tx3);\
    float T0 = fmaxf(Lx,  M01);                                               \
    float T1 = fmaxf(M01, tx2);                                               \
    float T2 = fmaxf(M12, tx3);                                               \
    float T3 = fmaxf(M23, Rx);                                                \
    float o0 = fmaf(eN[j][0]-sO[j][0], T0, sO[j][0]);                         \
    float o1 = fmaf(eN[j][1]-sO[j][1], T1, sO[j][1]);                         \
    float o2 = fmaf(eN[j][2]-sO[j][2], T2, sO[j][2]);                         \
    float o3 = fmaf(eN[j][3]-sO[j][3], T3, sO[j][3]);                         \
    sO[j][0] = CIN[0]; sO[j][1] = CIN[1]; sO[j][2] = CIN[2]; sO[j][3] = CIN[3];\
    eO[j][0] = en0;    eO[j][1] = en1;    eO[j][2] = en2;    eO[j][3] = en3;  \
    OUT[0] = o0; OUT[1] = o1; OUT[2] = o2; OUT[3] = o3;                       \
}

// ---------------- pass-1 row-step (proven R11 body) ----------------
#define DO_STEP(X, sN, sO, eN, eO)                                            \
{                                                                             \
    int x = (X);                                                              \
    float in0[4] = {nxt[0], nxt[1], nxt[2], nxt[3]};                          \
    int xn = x + 1;                                                           \
    if (colok && (unsigned)xn < (unsigned)HH){                                \
        float4 t4 = *(const float4*)(src + (size_t)xn*WW + gc);               \
        if (tens == 0){                                                       \
            t4.x = sigf(t4.x); t4.y = sigf(t4.y);                             \
            t4.z = sigf(t4.z); t4.w = sigf(t4.w);                             \
        }                                                                     \
        nxt[0]=t4.x; nxt[1]=t4.y; nxt[2]=t4.z; nxt[3]=t4.w;                   \
    } else {                                                                  \
        nxt[0]=PINF; nxt[1]=PINF; nxt[2]=PINF; nxt[3]=PINF;                   \
    }                                                                         \
    float o4[4];                                                              \
    STAGE(4, sN, sO, eN, eO, b3,  o4);                                        \
    STAGE(3, sN, sO, eN, eO, b2,  b3);                                        \
    STAGE(2, sN, sO, eN, eO, b1,  b2);                                        \
    STAGE(1, sN, sO, eN, eO, b0,  b1);                                        \
    STAGE(0, sN, sO, eN, eO, in0, b0);                                        \
    if (owned && (unsigned)(x - LAGOUT - r0) < (unsigned)RB){                 \
        *(float4*)(dst + (size_t)(x - LAGOUT)*WW + gc) =                      \
            make_float4(o4[0], o4[1], o4[2], o4[3]);                          \
    }                                                                         \
}

// ---------------- pass 1: iterations 1..5 + dice backfill blocks ----------
__global__ void __launch_bounds__(32, 12) k_skel1(const float* __restrict__ logits,
                                                  const float* __restrict__ target){
    const float PINF = __int_as_float(0x7f800000);
    const float NINF = __int_as_float(0xff800000);

    int gw   = blockIdx.x;
    if (gw >= NSKEL){
        dice_path(gw - NSKEL, logits, target);
        return;
    }
    int lane = threadIdx.x;
    int band = gw & 3;  int q = gw >> 2;
    int ct   = q % CTILES; q /= CTILES;
    int img  = q & 31;  int tens = q >> 5;

    const float* __restrict__ src = (tens ? target : logits) + (size_t)img*NPIX;
    float* __restrict__ dst = g_tmp[tens] + (size_t)img*NPIX;

    int r0 = band * RB;
    int c0 = ct*OWNC - HALO_C;
    int gc = c0 + (lane<<2);                 // lane's 4 global cols (mult of 4)
    bool colok = (gc >= 0) && (gc < WW);     // whole float4 in or out
    bool owned = (lane >= HALO_C/4) && (lane < (HALO_C+OWNC)/4) && colok;

    float sA[KF][4], sB[KF][4], eA[KF][4], eB[KF][4];
    float b0[4], b1[4], b2[4], b3[4];
    #pragma unroll
    for (int j = 0; j < KF; j++)
        #pragma unroll
        for (int v = 0; v < 4; v++){
            sA[j][v]=PINF; sB[j][v]=PINF; eA[j][v]=NINF; eB[j][v]=NINF;
        }
    #pragma unroll
    for (int v = 0; v < 4; v++){ b0[v]=PINF; b1[v]=PINF; b2[v]=PINF; b3[v]=PINF; }

    int x0 = r0 - 11;
    float nxt[4];
    if (colok && (unsigned)x0 < (unsigned)HH){
        float4 t4 = *(const float4*)(src + (size_t)x0*WW + gc);
        if (tens == 0){
            t4.x = sigf(t4.x); t4.y = sigf(t4.y);
            t4.z = sigf(t4.z); t4.w = sigf(t4.w);
        }
        nxt[0]=t4.x; nxt[1]=t4.y; nxt[2]=t4.z; nxt[3]=t4.w;
    } else {
        nxt[0]=PINF; nxt[1]=PINF; nxt[2]=PINF; nxt[3]=PINF;
    }

    for (int step = 0; step < NSTEPS; step += 2){
        DO_STEP(x0 + step,     sA, sB, eA, eB);
        DO_STEP(x0 + step + 1, sB, sA, eB, eA);
    }
}

// ---------------- pass-2 dual row-step: both tensors, fused skel-dice ------
#define DO_STEP2(X, sNP, sOP, eNP, eOP, sNT, sOT, eNT, eOT)                   \
{                                                                             \
    int x = (X);                                                              \
    float inP[4] = {nxtP[0], nxtP[1], nxtP[2], nxtP[3]};                      \
    float inT[4] = {nxtT[0], nxtT[1], nxtT[2], nxtT[3]};                      \
    int xn = x + 1;                                                           \
    if (colok && (unsigned)xn < (unsigned)HH){                                \
        float4 a4 = *(const float4*)(srcP + (size_t)xn*WW + gc);              \
        float4 c4 = *(const float4*)(srcT + (size_t)xn*WW + gc);              \
        nxtP[0]=a4.x; nxtP[1]=a4.y; nxtP[2]=a4.z; nxtP[3]=a4.w;               \
        nxtT[0]=c4.x; nxtT[1]=c4.y; nxtT[2]=c4.z; nxtT[3]=c4.w;               \
    } else {                                                                  \
        nxtP[0]=PINF; nxtP[1]=PINF; nxtP[2]=PINF; nxtP[3]=PINF;               \
        nxtT[0]=PINF; nxtT[1]=PINF; nxtT[2]=PINF; nxtT[3]=PINF;               \
    }                                                                         \
    float o4P[4], o4T[4];                                                     \
    STAGE(4, sNP, sOP, eNP, eOP, b3P, o4P);                                   \
    STAGE(4, sNT, sOT, eNT, eOT, b3T, o4T);                                   \
    STAGE(3, sNP, sOP, eNP, eOP, b2P, b3P);                                   \
    STAGE(3, sNT, sOT, eNT, eOT, b2T, b3T);                                   \
    STAGE(2, sNP, sOP, eNP, eOP, b1P, b2P);                                   \
    STAGE(2, sNT, sOT, eNT, eOT, b1T, b2T);                                   \
    STAGE(1, sNP, sOP, eNP, eOP, b0P, b1P);                                   \
    STAGE(1, sNT, sOT, eNT, eOT, b0T, b1T);                                   \
    STAGE(0, sNP, sOP, eNP, eOP, inP, b0P);                                   \
    STAGE(0, sNT, sOT, eNT, eOT, inT, b0T);                                   \
    if (owned && (unsigned)(x - LAGOUT - r0) < (unsigned)RB){                 \
        ssp  += (o4P[0]+o4P[1]) + (o4P[2]+o4P[3]);                            \
        sst  += (o4T[0]+o4T[1]) + (o4T[2]+o4T[3]);                            \
        sspt += (o4P[0]*o4T[0] + o4P[1]*o4T[1])                               \
              + (o4P[2]*o4T[2] + o4P[3]*o4T[3]);                              \
    }                                                                         \
}

// ---------------- pass 2: iterations 6..10 for BOTH tensors per warp, ------
// fused skeleton-dice sums (zero stores) + last-block finalize --------------
__global__ void __launch_bounds__(32) k_skel2(float* __restrict__ out){
    const float PINF = __int_as_float(0x7f800000);
    const float NINF = __int_as_float(0xff800000);

    int gw   = blockIdx.x;
    int lane = threadIdx.x;
    int band = gw & 3;  int q = gw >> 2;
    int ct   = q % CTILES;
    int img  = q / CTILES;

    const float* __restrict__ srcP = g_tmp[0] + (size_t)img*NPIX;
    const float* __restrict__ srcT = g_tmp[1] + (size_t)img*NPIX;

    int r0 = band * RB;
    int c0 = ct*OWNC - HALO_C;
    int gc = c0 + (lane<<2);
    bool colok = (gc >= 0) && (gc < WW);
    bool owned = (lane >= HALO_C/4) && (lane < (HALO_C+OWNC)/4) && colok;

    float sAP[KF][4], sBP[KF][4], eAP[KF][4], eBP[KF][4];
    float sAT[KF][4], sBT[KF][4], eAT[KF][4], eBT[KF][4];
    float b0P[4], b1P[4], b2P[4], b3P[4];
    float b0T[4], b1T[4], b2T[4], b3T[4];
    #pragma unroll
    for (int j = 0; j < KF; j++)
        #pragma unroll
        for (int v = 0; v < 4; v++){
            sAP[j][v]=PINF; sBP[j][v]=PINF; eAP[j][v]=NINF; eBP[j][v]=NINF;
            sAT[j][v]=PINF; sBT[j][v]=PINF; eAT[j][v]=NINF; eBT[j][v]=NINF;
        }
    #pragma unroll
    for (int v = 0; v < 4; v++){
        b0P[v]=PINF; b1P[v]=PINF; b2P[v]=PINF; b3P[v]=PINF;
        b0T[v]=PINF; b1T[v]=PINF; b2T[v]=PINF; b3T[v]=PINF;
    }

    int x0 = r0 - 11;
    float nxtP[4], nxtT[4];
    if (colok && (unsigned)x0 < (unsigned)HH){
        float4 a4 = *(const float4*)(srcP + (size_t)x0*WW + gc);
        float4 c4 = *(const float4*)(srcT + (size_t)x0*WW + gc);
        nxtP[0]=a4.x; nxtP[1]=a4.y; nxtP[2]=a4.z; nxtP[3]=a4.w;
        nxtT[0]=c4.x; nxtT[1]=c4.y; nxtT[2]=c4.z; nxtT[3]=c4.w;
    } else {
        nxtP[0]=PINF; nxtP[1]=PINF; nxtP[2]=PINF; nxtP[3]=PINF;
        nxtT[0]=PINF; nxtT[1]=PINF; nxtT[2]=PINF; nxtT[3]=PINF;
    }

    float ssp=0.f, sst=0.f, sspt=0.f;

    for (int step = 0; step < NSTEPS; step += 2){
        DO_STEP2(x0 + step,     sAP, sBP, eAP, eBP, sAT, sBT, eAT, eBT);
        DO_STEP2(x0 + step + 1, sBP, sAP, eBP, eAP, sBT, sAT, eBT, eAT);
    }

    #pragma unroll
    for (int o=16;o;o>>=1){
        ssp  += __shfl_down_sync(ALLM, ssp , o);
        sst  += __shfl_down_sync(ALLM, sst , o);
        sspt += __shfl_down_sync(ALLM, sspt, o);
    }
    if (lane == 0){
        atomicAdd(&g_acc[img][3], ssp);
        atomicAdd(&g_acc[img][4], sst);
        atomicAdd(&g_acc[img][5], sspt);
    }

    // last-block finalize: plain-dice atomics completed in pass-1 launch
    // (kernel boundary); skel-dice atomics counted here.
    __threadfence();
    unsigned old = 0;
    if (lane == 0) old = atomicAdd(&g_ctr, 1u);
    old = __shfl_sync(ALLM, old, 0);
    if (old == NSKEL2 - 1u){
        volatile float* a = &g_acc[lane][0];   // lane = image
        float d  = (2.0f*a[2] + SMOOTHF) / (a[0] + a[1] + SMOOTHF);
        float sd = (2.0f*a[5] + SMOOTHF) / (a[3] + a[4] + SMOOTHF);
        #pragma unroll
        for (int o=16;o;o>>=1){
            d  += __shfl_down_sync(ALLM, d , o);
            sd += __shfl_down_sync(ALLM, sd, o);
        }
        if (lane == 0){
            float dice  = d  * (1.0f/32.0f);
            float sdice = sd * (1.0f/32.0f);
            out[0] = 0.5f*(1.0f - dice) + 0.5f*(1.0f - sdice);
            out[1] = dice;
            out[2] = sdice;
        }
        // reset for next graph replay (globals start zeroed at module load,
        // so the invariant "g_acc == 0, g_ctr == 0 on entry" always holds)
        #pragma unroll
        for (int v = 0; v < 8; v++) g_acc[lane][v] = 0.0f;
        if (lane == 0) g_ctr = 0u;
    }
}

extern "C" void kernel_launch(void* const* d_in, const int* in_sizes, int n_in,
                              void* d_out, int out_size){
    const float* logits = (const float*)d_in[0];
    const float* target = (const float*)d_in[1];
    float* out = (float*)d_out;

    k_skel1<<<NSKEL + NDICE, 32>>>(logits, target);  // iters 1..5 + dice backfill
    k_skel2<<<NSKEL2, 32>>>(out);                    // iters 6..10 both tensors + sdice + finalize
    (void)in_sizes; (void)n_in; (void)out_size;
}

// round 13
// speedup vs baseline: 1.0574x; 1.0574x over previous
#include <cuda_runtime.h>

#define HH 512
#define WW 512
#define NPIX (HH*WW)
#define NIMG 32
#define SMOOTHF 1e-5f
#define KF 5            // fused skeletonize iterations per pass
#define HALO_C 12       // column halo per side (>= 2*KF, multiple of 4)
#define OWNC 104        // owned columns per warp window (128 - 2*HALO_C)
#define CTILES 5        // ceil(512/104)
#define RB 128          // rows per band
#define NBANDS 4
#define LAGOUT 14       // output lag: 3*(KF-1)+2
#define NSTEPS 154      // RB + 25 + 1 (even, x0 = r0-11)
#define ALLM 0xffffffffu
#define NSKEL (2*NIMG*CTILES*NBANDS)   // 1280 skel blocks per pass
#define NDICE 8192                     // dice backfill blocks in pass 1
#define NSDICE 8192                    // sdice backfill blocks in pass 2
#define PROD_PER_BAND 10u              // 2 tensors * 5 col-tiles

// Scratch (device globals: no allocation allowed; zero-initialized at load)
__device__ float    g_tmp [2][NIMG*NPIX];   // after iterations 1..5
__device__ float    g_skel[2][NIMG*NPIX];   // after iterations 6..10
__device__ float    g_acc [NIMG][8];        // 0:sp 1:st 2:spt 3:ssp 4:sst 5:sspt
__device__ unsigned g_ctr;                  // sdice completion counter
__device__ unsigned g_done[NIMG][NBANDS];   // pass-2 producer flags

__device__ __forceinline__ float sigf(float x){
    return __fdividef(1.0f, 1.0f + __expf(-x));
}

// ---- plain-dice backfill path (extra blocks of the pass-1 launch) ----
// One warp handles 1024 contiguous pixels of one image: 8 float4 per lane.
__device__ __forceinline__ void dice_path(int idx, const float* __restrict__ logits,
                                          const float* __restrict__ target){
    int img   = idx >> 8;          // 256 warps per image
    int chunk = idx & 255;
    int lane  = threadIdx.x;
    const float4* Lp = (const float4*)(logits + (size_t)img*NPIX);
    const float4* Tp = (const float4*)(target + (size_t)img*NPIX);
    int base = chunk*256 + lane;
    float4 l[8], t[8];
    #pragma unroll
    for (int i = 0; i < 8; i++) l[i] = Lp[base + i*32];
    #pragma unroll
    for (int i = 0; i < 8; i++) t[i] = Tp[base + i*32];
    float sp=0.f, st=0.f, spt=0.f;
    #pragma unroll
    for (int i = 0; i < 8; i++){
        float p;
        p = sigf(l[i].x); sp += p; st += t[i].x; spt += p*t[i].x;
        p = sigf(l[i].y); sp += p; st += t[i].y; spt += p*t[i].y;
        p = sigf(l[i].z); sp += p; st += t[i].z; spt += p*t[i].z;
        p = sigf(l[i].w); sp += p; st += t[i].w; spt += p*t[i].w;
    }
    #pragma unroll
    for (int o=16;o;o>>=1){
        sp  += __shfl_down_sync(ALLM, sp , o);
        st  += __shfl_down_sync(ALLM, st , o);
        spt += __shfl_down_sync(ALLM, spt, o);
    }
    if (lane == 0){
        atomicAdd(&g_acc[img][0], sp);
        atomicAdd(&g_acc[img][1], st);
        atomicAdd(&g_acc[img][2], spt);
    }
}

// ---- skeleton-dice backfill path (extra blocks of the pass-2 launch) ----
// Spins until its band's 10 producer blocks have published g_skel, then
// accumulates; the last of NSDICE blocks finalizes the 3 outputs and resets
// all globals for the next graph replay.
__device__ __forceinline__ void sdice_path(int idx, float* __restrict__ out){
    int img   = idx >> 8;
    int chunk = idx & 255;          // 1024 px = rows [2*chunk, 2*chunk+1]
    int band  = chunk >> 6;         // both rows inside one 128-row band
    int lane  = threadIdx.x;

    if (lane == 0){
        while (atomicAdd(&g_done[img][band], 0u) < PROD_PER_BAND) __nanosleep(200);
    }
    __syncwarp();
    __threadfence();                // order data reads after the flag read

    const float4* Pp = (const float4*)(g_skel[0] + (size_t)img*NPIX);
    const float4* Tp = (const float4*)(g_skel[1] + (size_t)img*NPIX);
    int base = chunk*256 + lane;
    float4 p[8], t[8];
    #pragma unroll
    for (int i = 0; i < 8; i++) p[i] = Pp[base + i*32];
    #pragma unroll
    for (int i = 0; i < 8; i++) t[i] = Tp[base + i*32];
    float sp=0.f, st=0.f, spt=0.f;
    #pragma unroll
    for (int i = 0; i < 8; i++){
        sp  += (p[i].x+p[i].y)+(p[i].z+p[i].w);
        st  += (t[i].x+t[i].y)+(t[i].z+t[i].w);
        spt += (p[i].x*t[i].x + p[i].y*t[i].y) + (p[i].z*t[i].z + p[i].w*t[i].w);
    }
    #pragma unroll
    for (int o=16;o;o>>=1){
        sp  += __shfl_down_sync(ALLM, sp , o);
        st  += __shfl_down_sync(ALLM, st , o);
        spt += __shfl_down_sync(ALLM, spt, o);
    }
    if (lane == 0){
        atomicAdd(&g_acc[img][3], sp);
        atomicAdd(&g_acc[img][4], st);
        atomicAdd(&g_acc[img][5], spt);
    }

    // last-block finalize (plain-dice atomics sealed by the pass-1/pass-2
    // kernel boundary; skel-dice atomics counted here).
    __threadfence();
    unsigned old = 0;
    if (lane == 0) old = atomicAdd(&g_ctr, 1u);
    old = __shfl_sync(ALLM, old, 0);
    if (old == NSDICE - 1u){
        volatile float* a = &g_acc[lane][0];   // lane = image
        float d  = (2.0f*a[2] + SMOOTHF) / (a[0] + a[1] + SMOOTHF);
        float sd = (2.0f*a[5] + SMOOTHF) / (a[3] + a[4] + SMOOTHF);
        #pragma unroll
        for (int o=16;o;o>>=1){
            d  += __shfl_down_sync(ALLM, d , o);
            sd += __shfl_down_sync(ALLM, sd, o);
        }
        if (lane == 0){
            float dice  = d  * (1.0f/32.0f);
            float sdice = sd * (1.0f/32.0f);
            out[0] = 0.5f*(1.0f - dice) + 0.5f*(1.0f - sdice);
            out[1] = dice;
            out[2] = sdice;
        }
        // reset for next graph replay (globals start zeroed at module load,
        // so the invariant "all counters/accumulators == 0 on entry" holds)
        #pragma unroll
        for (int v = 0; v < 8; v++) g_acc[lane][v] = 0.0f;
        #pragma unroll
        for (int b = 0; b < NBANDS; b++) g_done[lane][b] = 0u;
        if (lane == 0) g_ctr = 0u;
    }
}

// One decoupled pipeline stage j. Fed row xr = x - 3j (value in CIN).
// State: sN[j] = In_j[xr-1], sO[j] = In_j[xr-2], eN[j] = E_j[xr-2],
// eO[j] = E_j[xr-3]. Computes E_j[xr-1] and O_j[xr-2] -> OUT.
// Rotation by role swap (zero MOVs). Output is NOT boundary-forced: at
// OOB rows/cols it becomes +INF or NaN; fminf/fmaxf drop NaN operands, so
// downstream min chains treat it exactly as the +INF sentinel. Only the
// eroded field needs explicit forcing (en -> -INF at OOB), since it feeds
// a max-pool where the neutral element differs.
#define STAGE(j, sN, sO, eN, eO, CIN, OUT)                                    \
{                                                                             \
    float vm0 = fminf(sO[j][0], fminf(sN[j][0], CIN[0]));                     \
    float vm1 = fminf(sO[j][1], fminf(sN[j][1], CIN[1]));                     \
    float vm2 = fminf(sO[j][2], fminf(sN[j][2], CIN[2]));                     \
    float vm3 = fminf(sO[j][3], fminf(sN[j][3], CIN[3]));                     \
    float Lm = __shfl_up_sync  (ALLM, vm3, 1);                                \
    float Rm = __shfl_down_sync(ALLM, vm0, 1);                                \
    float m01 = fminf(vm0, vm1), m12 = fminf(vm1, vm2), m23 = fminf(vm2, vm3);\
    float en0 = fminf(Lm,  m01);                                              \
    float en1 = fminf(m01, vm2);                                              \
    float en2 = fminf(m12, vm3);                                              \
    float en3 = fminf(m23, Rm);                                               \
    if (!(colok && (unsigned)(x - 3*(j) - 1) < (unsigned)HH)){                \
        en0 = NINF; en1 = NINF; en2 = NINF; en3 = NINF;                       \
    }                                                                         \
    float tx0 = fmaxf(eO[j][0], fmaxf(eN[j][0], en0));                        \
    float tx1 = fmaxf(eO[j][1], fmaxf(eN[j][1], en1));                        \
    float tx2 = fmaxf(eO[j][2], fmaxf(eN[j][2], en2));                        \
    float tx3 = fmaxf(eO[j][3], fmaxf(eN[j][3], en3));                        \
    float Lx = __shfl_up_sync  (ALLM, tx3, 1);                                \
    float Rx = __shfl_down_sync(ALLM, tx0, 1);                                \
    float M01 = fmaxf(tx0, tx1), M12 = fmaxf(tx1, tx2), M23 = fmaxf(tx2, tx3);\
    float T0 = fmaxf(Lx,  M01);                                               \
    float T1 = fmaxf(M01, tx2);                                               \
    float T2 = fmaxf(M12, tx3);                                               \
    float T3 = fmaxf(M23, Rx);                                                \
    float o0 = fmaf(eN[j][0]-sO[j][0], T0, sO[j][0]);                         \
    float o1 = fmaf(eN[j][1]-sO[j][1], T1, sO[j][1]);                         \
    float o2 = fmaf(eN[j][2]-sO[j][2], T2, sO[j][2]);                         \
    float o3 = fmaf(eN[j][3]-sO[j][3], T3, sO[j][3]);                         \
    sO[j][0] = CIN[0]; sO[j][1] = CIN[1]; sO[j][2] = CIN[2]; sO[j][3] = CIN[3];\
    eO[j][0] = en0;    eO[j][1] = en1;    eO[j][2] = en2;    eO[j][3] = en3;  \
    OUT[0] = o0; OUT[1] = o1; OUT[2] = o2; OUT[3] = o3;                       \
}

// One full row-step (proven R11 body). DOSIG constant-folds per call site.
#define DO_STEP(X, sN, sO, eN, eO, DOSIG)                                     \
{                                                                             \
    int x = (X);                                                              \
    float in0[4] = {nxt[0], nxt[1], nxt[2], nxt[3]};                          \
    int xn = x + 1;                                                           \
    if (colok && (unsigned)xn < (unsigned)HH){                                \
        float4 t4 = *(const float4*)(src + (size_t)xn*WW + gc);               \
        if (DOSIG){                                                           \
            t4.x = sigf(t4.x); t4.y = sigf(t4.y);                             \
            t4.z = sigf(t4.z); t4.w = sigf(t4.w);                             \
        }                                                                     \
        nxt[0]=t4.x; nxt[1]=t4.y; nxt[2]=t4.z; nxt[3]=t4.w;                   \
    } else {                                                                  \
        nxt[0]=PINF; nxt[1]=PINF; nxt[2]=PINF; nxt[3]=PINF;                   \
    }                                                                         \
    float o4[4];                                                              \
    STAGE(4, sN, sO, eN, eO, b3,  o4);                                        \
    STAGE(3, sN, sO, eN, eO, b2,  b3);                                        \
    STAGE(2, sN, sO, eN, eO, b1,  b2);                                        \
    STAGE(1, sN, sO, eN, eO, b0,  b1);                                        \
    STAGE(0, sN, sO, eN, eO, in0, b0);                                        \
    if (owned && (unsigned)(x - LAGOUT - r0) < (unsigned)RB){                 \
        *(float4*)(dst + (size_t)(x - LAGOUT)*WW + gc) =                      \
            make_float4(o4[0], o4[1], o4[2], o4[3]);                          \
    }                                                                         \
}

// Shared skel prologue/loop body emitted in both kernels.
#define SKEL_BODY(SRC_EXPR, DST_EXPR, DOSIG)                                  \
    int r0 = band * RB;                                                       \
    int c0 = ct*OWNC - HALO_C;                                                \
    int gc = c0 + (lane<<2);                                                  \
    bool colok = (gc >= 0) && (gc < WW);                                      \
    bool owned = (lane >= HALO_C/4) && (lane < (HALO_C+OWNC)/4) && colok;     \
    const float* __restrict__ src = (SRC_EXPR);                               \
    float* __restrict__ dst = (DST_EXPR);                                     \
    float sA[KF][4], sB[KF][4], eA[KF][4], eB[KF][4];                         \
    float b0[4], b1[4], b2[4], b3[4];                                         \
    _Pragma("unroll")                                                         \
    for (int j = 0; j < KF; j++)                                              \
        _Pragma("unroll")                                                     \
        for (int v = 0; v < 4; v++){                                          \
            sA[j][v]=PINF; sB[j][v]=PINF; eA[j][v]=NINF; eB[j][v]=NINF;       \
        }                                                                     \
    _Pragma("unroll")                                                         \
    for (int v = 0; v < 4; v++){ b0[v]=PINF; b1[v]=PINF; b2[v]=PINF; b3[v]=PINF; } \
    int x0 = r0 - 11;                                                         \
    float nxt[4];                                                             \
    if (colok && (unsigned)x0 < (unsigned)HH){                                \
        float4 t4 = *(const float4*)(src + (size_t)x0*WW + gc);               \
        if (DOSIG){                                                           \
            t4.x = sigf(t4.x); t4.y = sigf(t4.y);                             \
            t4.z = sigf(t4.z); t4.w = sigf(t4.w);                             \
        }                                                                     \
        nxt[0]=t4.x; nxt[1]=t4.y; nxt[2]=t4.z; nxt[3]=t4.w;                   \
    } else {                                                                  \
        nxt[0]=PINF; nxt[1]=PINF; nxt[2]=PINF; nxt[3]=PINF;                   \
    }                                                                         \
    for (int step = 0; step < NSTEPS; step += 2){                             \
        DO_STEP(x0 + step,     sA, sB, eA, eB, DOSIG);                        \
        DO_STEP(x0 + step + 1, sB, sA, eB, eA, DOSIG);                        \
    }

// ---------------- pass 1: iterations 1..5 + dice backfill blocks ----------
__global__ void __launch_bounds__(32, 12) k_skel1(const float* __restrict__ logits,
                                                  const float* __restrict__ target){
    const float PINF = __int_as_float(0x7f800000);
    const float NINF = __int_as_float(0xff800000);

    int gw = blockIdx.x;
    if (gw >= NSKEL){
        dice_path(gw - NSKEL, logits, target);
        return;
    }
    int lane = threadIdx.x;
    int band = gw & 3;  int q = gw >> 2;
    int ct   = q % CTILES; q /= CTILES;
    int img  = q & 31;  int tens = q >> 5;

    SKEL_BODY((tens ? target : logits) + (size_t)img*NPIX,
              g_tmp[tens] + (size_t)img*NPIX,
              (tens == 0))
}

// ---------------- pass 2: iterations 6..10 + sdice backfill blocks --------
__global__ void __launch_bounds__(32, 12) k_skel2(float* __restrict__ out){
    const float PINF = __int_as_float(0x7f800000);
    const float NINF = __int_as_float(0xff800000);

    int gw = blockIdx.x;
    if (gw >= NSKEL){
        sdice_path(gw - NSKEL, out);
        return;
    }
    int lane = threadIdx.x;
    int band = gw & 3;  int q = gw >> 2;
    int ct   = q % CTILES; q /= CTILES;
    int img  = q & 31;  int tens = q >> 5;

    SKEL_BODY(g_tmp[tens] + (size_t)img*NPIX,
              g_skel[tens] + (size_t)img*NPIX,
              0)

    // publish completion for this (img, band): release = fence + atomic
    __threadfence();
    if (lane == 0) atomicAdd(&g_done[img][band], 1u);
}

extern "C" void kernel_launch(void* const* d_in, const int* in_sizes, int n_in,
                              void* d_out, int out_size){
    const float* logits = (const float*)d_in[0];
    const float* target = (const float*)d_in[1];
    float* out = (float*)d_out;

    k_skel1<<<NSKEL + NDICE, 32>>>(logits, target);  // iters 1..5 + dice backfill
    k_skel2<<<NSKEL + NSDICE, 32>>>(out);            // iters 6..10 + sdice + finalize
    (void)in_sizes; (void)n_in; (void)out_size;
}

// round 14
// speedup vs baseline: 1.1239x; 1.0629x over previous
#include <cuda_runtime.h>

#define HH 512
#define WW 512
#define NPIX (HH*WW)
#define NIMG 32
#define SMOOTHF 1e-5f
#define KF 5            // fused skeletonize iterations per pass
#define HALO_C 12       // column halo per side (>= 2*KF, multiple of 4)
#define OWNC 104        // owned columns per warp window (128 - 2*HALO_C)
#define CTILES 5        // ceil(512/104)
#define RB 128          // rows per band
#define NBANDS 4
#define LAGOUT 14       // output lag: 3*(KF-1)+2
#define NSTEPS 154      // RB + 25 + 1 (even, x0 = r0-11)
#define ALLM 0xffffffffu
#define NSKEL (2*NIMG*CTILES*NBANDS)   // 1280 skel blocks per pass
#define NDICE 8192                     // dice backfill blocks
#define NSDICE 8192                    // sdice backfill blocks
#define PROD_PER_BAND 10u              // 2 tensors * 5 col-tiles
#define PROD_PER_IMG  20u              // CTILES * NBANDS pass-1 blocks per (img,tens)
// bid ranges (FIFO launch order): pass1 | dice | pass2 | sdice
#define BID_DICE   NSKEL
#define BID_PASS2  (NSKEL + NDICE)
#define BID_SDICE  (2*NSKEL + NDICE)
#define NBLK_TOTAL (2*NSKEL + NDICE + NSDICE)

// Scratch (device globals: no allocation allowed; zero-initialized at load)
__device__ float    g_tmp [2][NIMG*NPIX];   // after iterations 1..5
__device__ float    g_skel[2][NIMG*NPIX];   // after iterations 6..10
__device__ float    g_acc [NIMG][8];        // 0:sp 1:st 2:spt 3:ssp 4:sst 5:sspt
__device__ unsigned g_ctr;                  // sdice completion counter
__device__ unsigned g_done[NIMG][NBANDS];   // pass-2 producer flags (per img, band)
__device__ unsigned g_p1done[2][NIMG];      // pass-1 producer flags (per tens, img)

__device__ __forceinline__ float sigf(float x){
    return __fdividef(1.0f, 1.0f + __expf(-x));
}

// ---- plain-dice backfill path ----
// One warp handles 1024 contiguous pixels of one image: 8 float4 per lane.
__device__ __forceinline__ void dice_path(int idx, const float* __restrict__ logits,
                                          const float* __restrict__ target){
    int img   = idx >> 8;          // 256 warps per image
    int chunk = idx & 255;
    int lane  = threadIdx.x;
    const float4* Lp = (const float4*)(logits + (size_t)img*NPIX);
    const float4* Tp = (const float4*)(target + (size_t)img*NPIX);
    int base = chunk*256 + lane;
    float4 l[8], t[8];
    #pragma unroll
    for (int i = 0; i < 8; i++) l[i] = Lp[base + i*32];
    #pragma unroll
    for (int i = 0; i < 8; i++) t[i] = Tp[base + i*32];
    float sp=0.f, st=0.f, spt=0.f;
    #pragma unroll
    for (int i = 0; i < 8; i++){
        float p;
        p = sigf(l[i].x); sp += p; st += t[i].x; spt += p*t[i].x;
        p = sigf(l[i].y); sp += p; st += t[i].y; spt += p*t[i].y;
        p = sigf(l[i].z); sp += p; st += t[i].z; spt += p*t[i].z;
        p = sigf(l[i].w); sp += p; st += t[i].w; spt += p*t[i].w;
    }
    #pragma unroll
    for (int o=16;o;o>>=1){
        sp  += __shfl_down_sync(ALLM, sp , o);
        st  += __shfl_down_sync(ALLM, st , o);
        spt += __shfl_down_sync(ALLM, spt, o);
    }
    if (lane == 0){
        atomicAdd(&g_acc[img][0], sp);
        atomicAdd(&g_acc[img][1], st);
        atomicAdd(&g_acc[img][2], spt);
    }
}

// ---- skeleton-dice backfill path ----
// Spins until its band's 10 pass-2 producer blocks have published g_skel,
// then accumulates; the last of NSDICE blocks finalizes the 3 outputs and
// resets all globals for the next graph replay.
__device__ __forceinline__ void sdice_path(int idx, float* __restrict__ out){
    int img   = idx >> 8;
    int chunk = idx & 255;          // 1024 px = rows [2*chunk, 2*chunk+1]
    int band  = chunk >> 6;         // both rows inside one 128-row band
    int lane  = threadIdx.x;

    if (lane == 0){
        while (atomicAdd(&g_done[img][band], 0u) < PROD_PER_BAND) __nanosleep(200);
    }
    __syncwarp();
    __threadfence();                // order data reads after the flag read

    const float4* Pp = (const float4*)(g_skel[0] + (size_t)img*NPIX);
    const float4* Tp = (const float4*)(g_skel[1] + (size_t)img*NPIX);
    int base = chunk*256 + lane;
    float4 p[8], t[8];
    #pragma unroll
    for (int i = 0; i < 8; i++) p[i] = Pp[base + i*32];
    #pragma unroll
    for (int i = 0; i < 8; i++) t[i] = Tp[base + i*32];
    float sp=0.f, st=0.f, spt=0.f;
    #pragma unroll
    for (int i = 0; i < 8; i++){
        sp  += (p[i].x+p[i].y)+(p[i].z+p[i].w);
        st  += (t[i].x+t[i].y)+(t[i].z+t[i].w);
        spt += (p[i].x*t[i].x + p[i].y*t[i].y) + (p[i].z*t[i].z + p[i].w*t[i].w);
    }
    #pragma unroll
    for (int o=16;o;o>>=1){
        sp  += __shfl_down_sync(ALLM, sp , o);
        st  += __shfl_down_sync(ALLM, st , o);
        spt += __shfl_down_sync(ALLM, spt, o);
    }
    if (lane == 0){
        atomicAdd(&g_acc[img][3], sp);
        atomicAdd(&g_acc[img][4], st);
        atomicAdd(&g_acc[img][5], spt);
    }

    // last-block finalize (all other atomics are ordered before the counter
    // increments by the threadfences).
    __threadfence();
    unsigned old = 0;
    if (lane == 0) old = atomicAdd(&g_ctr, 1u);
    old = __shfl_sync(ALLM, old, 0);
    if (old == NSDICE - 1u){
        volatile float* a = &g_acc[lane][0];   // lane = image
        float d  = (2.0f*a[2] + SMOOTHF) / (a[0] + a[1] + SMOOTHF);
        float sd = (2.0f*a[5] + SMOOTHF) / (a[3] + a[4] + SMOOTHF);
        #pragma unroll
        for (int o=16;o;o>>=1){
            d  += __shfl_down_sync(ALLM, d , o);
            sd += __shfl_down_sync(ALLM, sd, o);
        }
        if (lane == 0){
            float dice  = d  * (1.0f/32.0f);
            float sdice = sd * (1.0f/32.0f);
            out[0] = 0.5f*(1.0f - dice) + 0.5f*(1.0f - sdice);
            out[1] = dice;
            out[2] = sdice;
        }
        // reset for next graph replay (globals start zeroed at module load,
        // so the invariant "all counters/accumulators == 0 on entry" holds)
        #pragma unroll
        for (int v = 0; v < 8; v++) g_acc[lane][v] = 0.0f;
        #pragma unroll
        for (int b = 0; b < NBANDS; b++) g_done[lane][b] = 0u;
        g_p1done[0][lane] = 0u;
        g_p1done[1][lane] = 0u;
        if (lane == 0) g_ctr = 0u;
    }
}

// One decoupled pipeline stage j. Fed row xr = x - 3j (value in CIN).
// State: sN[j] = In_j[xr-1], sO[j] = In_j[xr-2], eN[j] = E_j[xr-2],
// eO[j] = E_j[xr-3]. Computes E_j[xr-1] and O_j[xr-2] -> OUT.
// Rotation by role swap (zero MOVs). Output is NOT boundary-forced: at
// OOB rows/cols it becomes +INF or NaN; fminf/fmaxf drop NaN operands, so
// downstream min chains treat it exactly as the +INF sentinel. Only the
// eroded field needs explicit forcing (en -> -INF at OOB), since it feeds
// a max-pool where the neutral element differs.
#define STAGE(j, sN, sO, eN, eO, CIN, OUT)                                    \
{                                                                             \
    float vm0 = fminf(sO[j][0], fminf(sN[j][0], CIN[0]));                     \
    float vm1 = fminf(sO[j][1], fminf(sN[j][1], CIN[1]));                     \
    float vm2 = fminf(sO[j][2], fminf(sN[j][2], CIN[2]));                     \
    float vm3 = fminf(sO[j][3], fminf(sN[j][3], CIN[3]));                     \
    float Lm = __shfl_up_sync  (ALLM, vm3, 1);                                \
    float Rm = __shfl_down_sync(ALLM, vm0, 1);                                \
    float m01 = fminf(vm0, vm1), m12 = fminf(vm1, vm2), m23 = fminf(vm2, vm3);\
    float en0 = fminf(Lm,  m01);                                              \
    float en1 = fminf(m01, vm2);                                              \
    float en2 = fminf(m12, vm3);                                              \
    float en3 = fminf(m23, Rm);                                               \
    if (!(colok && (unsigned)(x - 3*(j) - 1) < (unsigned)HH)){                \
        en0 = NINF; en1 = NINF; en2 = NINF; en3 = NINF;                       \
    }                                                                         \
    float tx0 = fmaxf(eO[j][0], fmaxf(eN[j][0], en0));                        \
    float tx1 = fmaxf(eO[j][1], fmaxf(eN[j][1], en1));                        \
    float tx2 = fmaxf(eO[j][2], fmaxf(eN[j][2], en2));                        \
    float tx3 = fmaxf(eO[j][3], fmaxf(eN[j][3], en3));                        \
    float Lx = __shfl_up_sync  (ALLM, tx3, 1);                                \
    float Rx = __shfl_down_sync(ALLM, tx0, 1);                                \
    float M01 = fmaxf(tx0, tx1), M12 = fmaxf(tx1, tx2), M23 = fmaxf(tx2, tx3);\
    float T0 = fmaxf(Lx,  M01);                                               \
    float T1 = fmaxf(M01, tx2);                                               \
    float T2 = fmaxf(M12, tx3);                                               \
    float T3 = fmaxf(M23, Rx);                                                \
    float o0 = fmaf(eN[j][0]-sO[j][0], T0, sO[j][0]);                         \
    float o1 = fmaf(eN[j][1]-sO[j][1], T1, sO[j][1]);                         \
    float o2 = fmaf(eN[j][2]-sO[j][2], T2, sO[j][2]);                         \
    float o3 = fmaf(eN[j][3]-sO[j][3], T3, sO[j][3]);                         \
    sO[j][0] = CIN[0]; sO[j][1] = CIN[1]; sO[j][2] = CIN[2]; sO[j][3] = CIN[3];\
    eO[j][0] = en0;    eO[j][1] = en1;    eO[j][2] = en2;    eO[j][3] = en3;  \
    OUT[0] = o0; OUT[1] = o1; OUT[2] = o2; OUT[3] = o3;                       \
}

// One full row-step (proven body). DOSIG constant-folds per call site.
#define DO_STEP(X, sN, sO, eN, eO, DOSIG)                                     \
{                                                                             \
    int x = (X);                                                              \
    float in0[4] = {nxt[0], nxt[1], nxt[2], nxt[3]};                          \
    int xn = x + 1;                                                           \
    if (colok && (unsigned)xn < (unsigned)HH){                                \
        float4 t4 = *(const float4*)(src + (size_t)xn*WW + gc);               \
        if (DOSIG){                                                           \
            t4.x = sigf(t4.x); t4.y = sigf(t4.y);                             \
            t4.z = sigf(t4.z); t4.w = sigf(t4.w);                             \
        }                                                                     \
        nxt[0]=t4.x; nxt[1]=t4.y; nxt[2]=t4.z; nxt[3]=t4.w;                   \
    } else {                                                                  \
        nxt[0]=PINF; nxt[1]=PINF; nxt[2]=PINF; nxt[3]=PINF;                   \
    }                                                                         \
    float o4[4];                                                              \
    STAGE(4, sN, sO, eN, eO, b3,  o4);                                        \
    STAGE(3, sN, sO, eN, eO, b2,  b3);                                        \
    STAGE(2, sN, sO, eN, eO, b1,  b2);                                        \
    STAGE(1, sN, sO, eN, eO, b0,  b1);                                        \
    STAGE(0, sN, sO, eN, eO, in0, b0);                                        \
    if (owned && (unsigned)(x - LAGOUT - r0) < (unsigned)RB){                 \
        *(float4*)(dst + (size_t)(x - LAGOUT)*WW + gc) =                      \
            make_float4(o4[0], o4[1], o4[2], o4[3]);                          \
    }                                                                         \
}

// Shared skel prologue/loop body.
#define SKEL_BODY(SRC_EXPR, DST_EXPR, DOSIG)                                  \
    int r0 = band * RB;                                                       \
    int c0 = ct*OWNC - HALO_C;                                                \
    int gc = c0 + (lane<<2);                                                  \
    bool colok = (gc >= 0) && (gc < WW);                                      \
    bool owned = (lane >= HALO_C/4) && (lane < (HALO_C+OWNC)/4) && colok;     \
    const float* __restrict__ src = (SRC_EXPR);                               \
    float* __restrict__ dst = (DST_EXPR);                                     \
    float sA[KF][4], sB[KF][4], eA[KF][4], eB[KF][4];                         \
    float b0[4], b1[4], b2[4], b3[4];                                         \
    _Pragma("unroll")                                                         \
    for (int j = 0; j < KF; j++)                                              \
        _Pragma("unroll")                                                     \
        for (int v = 0; v < 4; v++){                                          \
            sA[j][v]=PINF; sB[j][v]=PINF; eA[j][v]=NINF; eB[j][v]=NINF;       \
        }                                                                     \
    _Pragma("unroll")                                                         \
    for (int v = 0; v < 4; v++){ b0[v]=PINF; b1[v]=PINF; b2[v]=PINF; b3[v]=PINF; } \
    int x0 = r0 - 11;                                                         \
    float nxt[4];                                                             \
    if (colok && (unsigned)x0 < (unsigned)HH){                                \
        float4 t4 = *(const float4*)(src + (size_t)x0*WW + gc);               \
        if (DOSIG){                                                           \
            t4.x = sigf(t4.x); t4.y = sigf(t4.y);                             \
            t4.z = sigf(t4.z); t4.w = sigf(t4.w);                             \
        }                                                                     \
        nxt[0]=t4.x; nxt[1]=t4.y; nxt[2]=t4.z; nxt[3]=t4.w;                   \
    } else {                                                                  \
        nxt[0]=PINF; nxt[1]=PINF; nxt[2]=PINF; nxt[3]=PINF;                   \
    }                                                                         \
    for (int step = 0; step < NSTEPS; step += 2){                             \
        DO_STEP(x0 + step,     sA, sB, eA, eB, DOSIG);                        \
        DO_STEP(x0 + step + 1, sB, sA, eB, eA, DOSIG);                        \
    }

// ---------------- single fused launch: pass1 | dice | pass2 | sdice --------
__global__ void __launch_bounds__(32, 12) k_all(const float* __restrict__ logits,
                                                const float* __restrict__ target,
                                                float* __restrict__ out){
    const float PINF = __int_as_float(0x7f800000);
    const float NINF = __int_as_float(0xff800000);

    int gw   = blockIdx.x;
    int lane = threadIdx.x;

    if (gw < NSKEL){
        // ---- pass 1: iterations 1..5 ----
        int band = gw & 3;  int q = gw >> 2;
        int ct   = q % CTILES; q /= CTILES;
        int img  = q & 31;  int tens = q >> 5;
        {
            SKEL_BODY((tens ? target : logits) + (size_t)img*NPIX,
                      g_tmp[tens] + (size_t)img*NPIX,
                      (tens == 0))
        }
        // publish: release = fence + atomic per (tens, img)
        __threadfence();
        if (lane == 0) atomicAdd(&g_p1done[tens][img], 1u);
    } else if (gw < BID_PASS2){
        // ---- plain-dice backfill ----
        dice_path(gw - BID_DICE, logits, target);
    } else if (gw < BID_SDICE){
        // ---- pass 2: iterations 6..10 (waits for its (tens,img) inputs) ----
        int idx  = gw - BID_PASS2;
        int band = idx & 3;  int q = idx >> 2;
        int ct   = q % CTILES; q /= CTILES;
        int img  = q & 31;  int tens = q >> 5;

        if (lane == 0){
            while (atomicAdd(&g_p1done[tens][img], 0u) < PROD_PER_IMG) __nanosleep(200);
        }
        __syncwarp();
        __threadfence();            // order g_tmp reads after the flag read
        {
            SKEL_BODY(g_tmp[tens] + (size_t)img*NPIX,
                      g_skel[tens] + (size_t)img*NPIX,
                      0)
        }
        // publish completion for this (img, band)
        __threadfence();
        if (lane == 0) atomicAdd(&g_done[img][band], 1u);
    } else {
        // ---- skeleton-dice backfill + finalize ----
        sdice_path(gw - BID_SDICE, out);
    }
}

extern "C" void kernel_launch(void* const* d_in, const int* in_sizes, int n_in,
                              void* d_out, int out_size){
    const float* logits = (const float*)d_in[0];
    const float* target = (const float*)d_in[1];
    float* out = (float*)d_out;

    k_all<<<NBLK_TOTAL, 32>>>(logits, target, out);
    (void)in_sizes; (void)n_in; (void)out_size;
}